// round 1
// baseline (speedup 1.0000x reference)
#include <cuda_runtime.h>
#include <cstdint>

// Problem constants
#define SEQ   2048
#define HID   512
#define TAPS  64
#define HC    256      // channels per block (one per thread)
#define SC    256      // seq positions per block
#define UGRP  16       // outputs per inner group (software pipeline)

__constant__ float kScale = 0.022097086912079608f; // 1/sqrt(2048)

// Kernel 1: circular depthwise conv (64 taps) + residual.
// Thread owns one hidden channel; sliding window + weights live in registers.
__global__ __launch_bounds__(HC, 1) void conv_res_kernel(
    const float* __restrict__ x,
    const float* __restrict__ w,
    float* __restrict__ out)
{
    const int c  = blockIdx.y * HC + threadIdx.x;   // channel
    const int b  = blockIdx.z;                      // batch
    const int s0 = blockIdx.x * SC;                 // chunk start (multiple of SC)

    const float* __restrict__ xb = x   + (size_t)b * (SEQ * HID) + c;
    float*       __restrict__ ob = out + (size_t)b * (SEQ * HID) + c;

    // Weights for this channel: w[1, TAPS, HID] -> w[k*HID + c]
    float wr[TAPS];
#pragma unroll
    for (int k = 0; k < TAPS; ++k) wr[k] = w[k * HID + c];

    // History window: win[i] = x[b, (sb - 63 + i) mod SEQ, c], i = 0..62
    float win[TAPS - 1];
#pragma unroll
    for (int i = 0; i < TAPS - 1; ++i) {
        int row = (s0 + i + (SEQ - (TAPS - 1))) & (SEQ - 1);   // s0 - 63 + i  (mod SEQ)
        win[i] = xb[row * HID];
    }

    // Current group of UGRP inputs, plus prefetch buffer for the next group.
    float cur[UGRP], nxt[UGRP];
#pragma unroll
    for (int j = 0; j < UGRP; ++j) cur[j] = xb[(s0 + j) * HID];

    for (int tt = 0; tt < SC; tt += UGRP) {
        const int sb = s0 + tt;

        // Prefetch next group's inputs (mask keeps the tail in-range; values unused).
        const int nb = sb + UGRP;
#pragma unroll
        for (int j = 0; j < UGRP; ++j)
            nxt[j] = xb[((nb + j) & (SEQ - 1)) * HID];

        // Compute UGRP outputs; all window/cur indices are compile-time constants.
#pragma unroll
        for (int j = 0; j < UGRP; ++j) {
            float acc0 = 0.f, acc1 = 0.f;   // two partial chains for ILP
#pragma unroll
            for (int k = 0; k < TAPS; k += 2) {
                {
                    const int idx = j - k;
                    const float xv = (idx >= 0) ? cur[(idx >= 0) ? idx : 0]
                                                : win[(idx >= 0) ? 0 : (TAPS - 1 + idx)];
                    acc0 += wr[k] * xv;
                }
                {
                    const int idx = j - (k + 1);
                    const float xv = (idx >= 0) ? cur[(idx >= 0) ? idx : 0]
                                                : win[(idx >= 0) ? 0 : (TAPS - 1 + idx)];
                    acc1 += wr[k + 1] * xv;
                }
            }
            ob[(sb + j) * HID] = (acc0 + acc1) * kScale + cur[j];
        }

        // Slide the window forward by UGRP.
#pragma unroll
        for (int i = 0; i < TAPS - 1 - UGRP; ++i) win[i] = win[i + UGRP];
#pragma unroll
        for (int i = 0; i < UGRP; ++i) win[TAPS - 1 - UGRP + i] = cur[i];
#pragma unroll
        for (int j = 0; j < UGRP; ++j) cur[j] = nxt[j];
    }
}

// Kernel 2: in-place LayerNorm over the hidden dim (512), one row per block.
__global__ __launch_bounds__(128, 16) void ln_kernel(
    float* __restrict__ out,
    const float* __restrict__ gamma,
    const float* __restrict__ beta)
{
    __shared__ float ssum[4], ssq[4];

    float4* __restrict__ p = reinterpret_cast<float4*>(out + (size_t)blockIdx.x * HID);
    const int t = threadIdx.x;

    float4 v = p[t];
    float s = v.x + v.y + v.z + v.w;
    float q = v.x * v.x + v.y * v.y + v.z * v.z + v.w * v.w;

#pragma unroll
    for (int o = 16; o > 0; o >>= 1) {
        s += __shfl_xor_sync(0xFFFFFFFFu, s, o);
        q += __shfl_xor_sync(0xFFFFFFFFu, q, o);
    }
    if ((t & 31) == 0) { ssum[t >> 5] = s; ssq[t >> 5] = q; }
    __syncthreads();

    s = ssum[0] + ssum[1] + ssum[2] + ssum[3];
    q = ssq[0]  + ssq[1]  + ssq[2]  + ssq[3];

    const float mean = s * (1.0f / HID);
    const float var  = q * (1.0f / HID) - mean * mean;
    const float inv  = rsqrtf(var + 1e-12f);

    const float4 g  = reinterpret_cast<const float4*>(gamma)[t];
    const float4 be = reinterpret_cast<const float4*>(beta)[t];

    v.x = g.x * (v.x - mean) * inv + be.x;
    v.y = g.y * (v.y - mean) * inv + be.y;
    v.z = g.z * (v.z - mean) * inv + be.z;
    v.w = g.w * (v.w - mean) * inv + be.w;
    p[t] = v;
}

extern "C" void kernel_launch(void* const* d_in, const int* in_sizes, int n_in,
                              void* d_out, int out_size)
{
    const float* x     = (const float*)d_in[0];   // [B, 2048, 512] f32
    const float* w     = (const float*)d_in[1];   // [1, 64, 512]   f32
    const float* gamma = (const float*)d_in[2];   // [512]          f32
    const float* beta  = (const float*)d_in[3];   // [512]          f32
    float* out = (float*)d_out;                   // [B, 2048, 512] f32

    const int B = in_sizes[0] / (SEQ * HID);

    dim3 g1(SEQ / SC, HID / HC, B);
    conv_res_kernel<<<g1, HC>>>(x, w, out);

    ln_kernel<<<B * SEQ, 128>>>(out, gamma, beta);
}

// round 2
// speedup vs baseline: 1.1184x; 1.1184x over previous
#include <cuda_runtime.h>
#include <cstdint>

#define SEQ   2048
#define HID   512
#define TAPS  64
#define SC    128      // seq positions per block
#define UGRP  8        // outputs per inner group
#define HTAPS 32       // taps per thread-half
#define WSPAN (HTAPS + UGRP - 1)   // 39 live window rows per half

typedef unsigned long long u64;

__device__ __forceinline__ u64 fma2(u64 a, u64 b, u64 c) {
    u64 d;
    asm("fma.rn.f32x2 %0, %1, %2, %3;" : "=l"(d) : "l"(a), "l"(b), "l"(c));
    return d;
}
__device__ __forceinline__ u64 add2(u64 a, u64 b) {
    u64 d;
    asm("add.rn.f32x2 %0, %1, %2;" : "=l"(d) : "l"(a), "l"(b));
    return d;
}

// Circular depthwise conv (64 taps) + residual, packed f32x2.
// 256 threads: thread = (channel-pair p in [0,128), tap-half h in {0,1}).
// Each thread computes 32-tap partials for 8 rows; halves combine via smem.
__global__ __launch_bounds__(256, 1) void conv_res_kernel(
    const float* __restrict__ x,
    const float* __restrict__ w,
    float* __restrict__ out)
{
    const int tid = threadIdx.x;
    const int p   = tid & 127;          // channel pair within block
    const int h   = tid >> 7;           // tap half: 0 -> taps 0..31, 1 -> taps 32..63
    const int c   = blockIdx.y * 256 + p * 2;
    const int b   = blockIdx.z;
    const int s0  = blockIdx.x * SC;

    const u64* __restrict__ xb =
        reinterpret_cast<const u64*>(x + (size_t)b * (SEQ * HID) + c);   // stride HID/2 per row
    u64* __restrict__ ob =
        reinterpret_cast<u64*>(out + (size_t)b * (SEQ * HID) + c);

    // Weights: this half's 32 taps for this channel pair.
    u64 wr[HTAPS];
#pragma unroll
    for (int k = 0; k < HTAPS; ++k)
        wr[k] = *reinterpret_cast<const u64*>(w + (k + HTAPS * h) * HID + c);

    // Window: win[i] = x[(s0 - 31 - 32h + i) mod SEQ]  (39 rows)
    u64 win[WSPAN];
#pragma unroll
    for (int i = 0; i < WSPAN; ++i) {
        int row = (s0 + SEQ - (HTAPS - 1) - HTAPS * h + i) & (SEQ - 1);
        win[i] = xb[row * (HID / 2)];
    }

    __shared__ u64 part[2][UGRP][128];

    const float ks = 0.022097086912079608f;   // 1/sqrt(2048)
    const u64 sc2 = ((u64)__float_as_uint(ks) << 32) | (u64)__float_as_uint(ks);

    for (int g = 0; g < SC / UGRP; ++g) {
        const int sb = s0 + g * UGRP;

        // Prefetch the next UGRP window rows (used after compute).
        u64 nxt[UGRP];
#pragma unroll
        for (int i = 0; i < UGRP; ++i) {
            int row = (sb + UGRP - HTAPS * h + i + SEQ) & (SEQ - 1);
            nxt[i] = xb[row * (HID / 2)];
        }

        // 32-tap partials for UGRP rows. y_h[sb+j] = sum_k wr[k]*win[31+j-k]
        u64 acc[UGRP];
#pragma unroll
        for (int j = 0; j < UGRP; ++j) acc[j] = 0ull;   // +0.0f pair
#pragma unroll
        for (int k = 0; k < HTAPS; ++k) {
#pragma unroll
            for (int j = 0; j < UGRP; ++j)
                acc[j] = fma2(wr[k], win[HTAPS - 1 + j - k], acc[j]);
        }

        const int buf = g & 1;
        if (h) {
#pragma unroll
            for (int j = 0; j < UGRP; ++j) part[buf][j][p] = acc[j];
        }
        __syncthreads();
        if (!h) {
            // Combine halves, scale, add residual (= window top rows), store.
#pragma unroll
            for (int j = 0; j < UGRP; ++j) {
                u64 tot = add2(acc[j], part[buf][j][p]);
                ob[(sb + j) * (HID / 2)] = fma2(tot, sc2, win[HTAPS - 1 + j]);
            }
        }

        // Slide window by UGRP.
#pragma unroll
        for (int i = 0; i < WSPAN - UGRP; ++i) win[i] = win[i + UGRP];
#pragma unroll
        for (int i = 0; i < UGRP; ++i) win[WSPAN - UGRP + i] = nxt[i];
    }
}

// In-place LayerNorm over hidden dim (512), one row per block.
__global__ __launch_bounds__(128, 16) void ln_kernel(
    float* __restrict__ out,
    const float* __restrict__ gamma,
    const float* __restrict__ beta)
{
    __shared__ float ssum[4], ssq[4];

    float4* __restrict__ pr = reinterpret_cast<float4*>(out + (size_t)blockIdx.x * HID);
    const int t = threadIdx.x;

    float4 v = pr[t];
    float s = v.x + v.y + v.z + v.w;
    float q = v.x * v.x + v.y * v.y + v.z * v.z + v.w * v.w;

#pragma unroll
    for (int o = 16; o > 0; o >>= 1) {
        s += __shfl_xor_sync(0xFFFFFFFFu, s, o);
        q += __shfl_xor_sync(0xFFFFFFFFu, q, o);
    }
    if ((t & 31) == 0) { ssum[t >> 5] = s; ssq[t >> 5] = q; }
    __syncthreads();

    s = ssum[0] + ssum[1] + ssum[2] + ssum[3];
    q = ssq[0]  + ssq[1]  + ssq[2]  + ssq[3];

    const float mean = s * (1.0f / HID);
    const float var  = q * (1.0f / HID) - mean * mean;
    const float inv  = rsqrtf(var + 1e-12f);

    const float4 g  = reinterpret_cast<const float4*>(gamma)[t];
    const float4 be = reinterpret_cast<const float4*>(beta)[t];

    v.x = g.x * (v.x - mean) * inv + be.x;
    v.y = g.y * (v.y - mean) * inv + be.y;
    v.z = g.z * (v.z - mean) * inv + be.z;
    v.w = g.w * (v.w - mean) * inv + be.w;
    pr[t] = v;
}

extern "C" void kernel_launch(void* const* d_in, const int* in_sizes, int n_in,
                              void* d_out, int out_size)
{
    const float* x     = (const float*)d_in[0];   // [B, 2048, 512] f32
    const float* w     = (const float*)d_in[1];   // [1, 64, 512]   f32
    const float* gamma = (const float*)d_in[2];   // [512]          f32
    const float* beta  = (const float*)d_in[3];   // [512]          f32
    float* out = (float*)d_out;

    const int B = in_sizes[0] / (SEQ * HID);

    dim3 g1(SEQ / SC, HID / 256, B);              // (16, 2, B)
    conv_res_kernel<<<g1, 256>>>(x, w, out);

    ln_kernel<<<B * SEQ, 128>>>(out, gamma, beta);
}

// round 3
// speedup vs baseline: 1.2371x; 1.1061x over previous
#include <cuda_runtime.h>
#include <cstdint>

#define SEQ   2048
#define HID   512
#define TAPS  64
#define SC    64       // seq rows per CTA
#define UGRP  8        // rows per inner group
#define HTAPS 32       // taps per thread-half
#define WSPAN (HTAPS + UGRP - 1)   // 39 live window rows per half
#define HBUF_PAIRS 256             // 512 channels as u64 pairs per row

typedef unsigned long long u64;

__device__ __forceinline__ u64 fma2(u64 a, u64 b, u64 c) {
    u64 d;
    asm("fma.rn.f32x2 %0, %1, %2, %3;" : "=l"(d) : "l"(a), "l"(b), "l"(c));
    return d;
}
__device__ __forceinline__ u64 add2(u64 a, u64 b) {
    u64 d;
    asm("add.rn.f32x2 %0, %1, %2;" : "=l"(d) : "l"(a), "l"(b));
    return d;
}
__device__ __forceinline__ float lo32(u64 v) { return __uint_as_float((unsigned)v); }
__device__ __forceinline__ float hi32(u64 v) { return __uint_as_float((unsigned)(v >> 32)); }
__device__ __forceinline__ u64 pack2(float l, float h) {
    return ((u64)__float_as_uint(h) << 32) | (u64)__float_as_uint(l);
}

// Fused: circular depthwise conv (64 taps, packed f32x2) + residual + LayerNorm.
// CTA = 64 seq rows x all 512 channels (two 256-channel passes).
// 256 threads = 128 channel-pairs x 2 tap-halves.
extern __shared__ u64 hbuf[];   // [SC][HBUF_PAIRS] = 128 KB

__global__ __launch_bounds__(256, 1) void fconv_ln_kernel(
    const float* __restrict__ x,
    const float* __restrict__ w,
    const float* __restrict__ gamma,
    const float* __restrict__ beta,
    float* __restrict__ out)
{
    const int tid = threadIdx.x;
    const int p   = tid & 127;          // channel pair within group
    const int h   = tid >> 7;           // tap half: 0 -> taps 0..31, 1 -> 32..63
    const int b   = blockIdx.y;
    const int s0  = blockIdx.x * SC;

    const float ks = 0.022097086912079608f;   // 1/sqrt(2048)
    const u64 sc2 = pack2(ks, ks);

#pragma unroll 1
    for (int cg = 0; cg < 2; ++cg) {
        const int c = cg * 256 + p * 2;
        const u64* __restrict__ xb =
            reinterpret_cast<const u64*>(x + (size_t)b * (SEQ * HID) + c);
        const int slotc = cg * 128 + p;

        // Weights: this half's 32 taps for this channel pair.
        u64 wr[HTAPS];
#pragma unroll
        for (int k = 0; k < HTAPS; ++k)
            wr[k] = *reinterpret_cast<const u64*>(w + (k + HTAPS * h) * HID + c);

        // Window: win[i] = x[(s0 - 31 - 32h + i) mod SEQ], covers up to s0+7 (h=0).
        u64 win[WSPAN];
#pragma unroll
        for (int i = 0; i < WSPAN; ++i) {
            int row = (s0 + SEQ - (HTAPS - 1) - HTAPS * h + i) & (SEQ - 1);
            win[i] = xb[row * (HID / 2)];
        }

#pragma unroll 1
        for (int g = 0; g < SC / UGRP; ++g) {
            const int sb = s0 + g * UGRP;
            const int rl = g * UGRP;        // local row base

            // Prefetch next UGRP window rows.
            u64 nxt[UGRP];
#pragma unroll
            for (int i = 0; i < UGRP; ++i) {
                int row = (sb + UGRP - HTAPS * h + i + SEQ) & (SEQ - 1);
                nxt[i] = xb[row * (HID / 2)];
            }

            // 32-tap partials for UGRP rows.
            u64 acc[UGRP];
#pragma unroll
            for (int j = 0; j < UGRP; ++j) acc[j] = 0ull;
#pragma unroll
            for (int k = 0; k < HTAPS; ++k) {
#pragma unroll
                for (int j = 0; j < UGRP; ++j)
                    acc[j] = fma2(wr[k], win[HTAPS - 1 + j - k], acc[j]);
            }

            if (h) {
#pragma unroll
                for (int j = 0; j < UGRP; ++j)
                    hbuf[(rl + j) * HBUF_PAIRS + slotc] = acc[j];
            }
            __syncthreads();
            if (!h) {
#pragma unroll
                for (int j = 0; j < UGRP; ++j) {
                    u64 tot = add2(acc[j], hbuf[(rl + j) * HBUF_PAIRS + slotc]);
                    hbuf[(rl + j) * HBUF_PAIRS + slotc] =
                        fma2(tot, sc2, win[HTAPS - 1 + j]);   // + residual
                }
            }

            // Slide window by UGRP.
#pragma unroll
            for (int i = 0; i < WSPAN - UGRP; ++i) win[i] = win[i + UGRP];
#pragma unroll
            for (int i = 0; i < UGRP; ++i) win[WSPAN - UGRP + i] = nxt[i];
        }
    }
    __syncthreads();

    // ---- LayerNorm epilogue: one warp per row, 8 rows per warp ----
    const int wid  = tid >> 5;
    const int lane = tid & 31;

    // Preload gamma/beta pairs for this lane's strided pair indices.
    u64 g8[8], b8[8];
#pragma unroll
    for (int k = 0; k < 8; ++k) {
        g8[k] = reinterpret_cast<const u64*>(gamma)[lane + 32 * k];
        b8[k] = reinterpret_cast<const u64*>(beta)[lane + 32 * k];
    }

    float* __restrict__ ob = out + (size_t)b * (SEQ * HID) + (size_t)s0 * HID;

#pragma unroll 1
    for (int r = wid; r < SC; r += 8) {
        u64 v[8];
        float s = 0.f, q = 0.f;
#pragma unroll
        for (int k = 0; k < 8; ++k) {
            v[k] = hbuf[r * HBUF_PAIRS + lane + 32 * k];
            float a = lo32(v[k]), bb = hi32(v[k]);
            s += a + bb;
            q += a * a + bb * bb;
        }
#pragma unroll
        for (int o = 16; o > 0; o >>= 1) {
            s += __shfl_xor_sync(0xFFFFFFFFu, s, o);
            q += __shfl_xor_sync(0xFFFFFFFFu, q, o);
        }
        const float mean = s * (1.0f / HID);
        const float var  = q * (1.0f / HID) - mean * mean;
        const float inv  = rsqrtf(var + 1e-12f);

        u64* __restrict__ orow = reinterpret_cast<u64*>(ob + r * HID);
#pragma unroll
        for (int k = 0; k < 8; ++k) {
            float a = (lo32(v[k]) - mean) * inv;
            float bb = (hi32(v[k]) - mean) * inv;
            float ro = lo32(g8[k]) * a + lo32(b8[k]);
            float rh = hi32(g8[k]) * bb + hi32(b8[k]);
            orow[lane + 32 * k] = pack2(ro, rh);
        }
    }
}

extern "C" void kernel_launch(void* const* d_in, const int* in_sizes, int n_in,
                              void* d_out, int out_size)
{
    const float* x     = (const float*)d_in[0];   // [B, 2048, 512] f32
    const float* w     = (const float*)d_in[1];   // [1, 64, 512]   f32
    const float* gamma = (const float*)d_in[2];   // [512]          f32
    const float* beta  = (const float*)d_in[3];   // [512]          f32
    float* out = (float*)d_out;

    const int B = in_sizes[0] / (SEQ * HID);
    const int smem = SC * HBUF_PAIRS * sizeof(u64);   // 128 KB

    static bool attr_set = false;
    if (!attr_set) {
        cudaFuncSetAttribute(fconv_ln_kernel,
                             cudaFuncAttributeMaxDynamicSharedMemorySize, smem);
        attr_set = true;
    }

    dim3 grid(SEQ / SC, B);   // (32, B)
    fconv_ln_kernel<<<grid, 256, smem>>>(x, w, gamma, beta, out);
}